// round 12
// baseline (speedup 1.0000x reference)
#include <cuda_runtime.h>
#include <cstdint>

#define NR      116
#define NRW     58             // packed count words per thread (2 regions/u32)
#define NT      224            // threads per block (7 warps)
#define NW      7              // warps per block
#define GRID    152            // one CTA per SM (GB300 = 152 SMs)
#define NTOT    (16*3*512*512) // 12,582,912
#define NV4     (NTOT/4)       // 3,145,728
#define ST      6              // cp.async pipeline stages (deep ring)

// Shared layout (dynamic):
//   f32  sumh[NR*NT]               103,936 B   (bank = tid -> conflict-free)
//   u32  cnth[NRW*NT]               51,968 B   (bank = tid -> conflict-free)
//   stages[ST]: {R float4[NT]; F float4[NT]; M int4[NT]}  6 x 10,752 B
#define SUM_BYTES   (NR * NT * 4)
#define CNT_BYTES   (NRW * NT * 4)
#define STG_ARR     (NT * 16)                 // 3584 B per array per stage
#define STG_STRIDE  (3 * STG_ARR)             // 10752 B per stage
#define SMEM_TOTAL  (SUM_BYTES + CNT_BYTES + ST * STG_STRIDE)  // 220,416 B

// Per-block partial (sum, count) per region + last-block ticket.
__device__ float2   g_part[GRID * NR];
__device__ unsigned g_ticket = 0;

__device__ __forceinline__ uint32_t smem_u32(const void* p)
{
    return (uint32_t)__cvta_generic_to_shared(p);
}

// Issue one stage's 3 x 16B cp.async into this thread's private slot, then
// close the group (empty group when invalid keeps group counting uniform).
__device__ __forceinline__ void stage_fill(uint32_t slot,
                                           const float4* Rp, const float4* Fp,
                                           const int4* Mp, int p, bool valid)
{
    if (valid) {
        asm volatile(
            "cp.async.cg.shared.global [%0], [%1], 16;\n\t"
            "cp.async.cg.shared.global [%2], [%3], 16;\n\t"
            "cp.async.cg.shared.global [%4], [%5], 16;\n"
            :: "r"(slot),               "l"(Rp + p),
               "r"(slot + STG_ARR),     "l"(Fp + p),
               "r"(slot + 2 * STG_ARR), "l"(Mp + p)
            : "memory");
    }
    asm volatile("cp.async.commit_group;" ::: "memory");
}

// Accumulate one scalar: f32 sum slot + packed u16x2 count slot.
__device__ __forceinline__ void acc1(float* sum0, unsigned* cnt0,
                                     float x, float y, int r)
{
    sum0[r * NT] += fabsf(x - y);
    cnt0[(r >> 1) * NT] += 1u << ((r & 1) << 4);
}

__device__ __forceinline__ void acc4(float* sum0, unsigned* cnt0,
                                     float4 a, float4 b, int4 m)
{
    acc1(sum0, cnt0, a.x, b.x, m.x);
    acc1(sum0, cnt0, a.y, b.y, m.y);
    acc1(sum0, cnt0, a.z, b.z, m.z);
    acc1(sum0, cnt0, a.w, b.w, m.w);
}

__global__ void __launch_bounds__(NT, 1)
fused_kernel(const float* __restrict__ realp,
             const float* __restrict__ fakep,
             const int*   __restrict__ rmapp,
             float* __restrict__ out)
{
    extern __shared__ unsigned char smem_raw[];
    float*         sumh = (float*)smem_raw;
    unsigned*      cnth = (unsigned*)(smem_raw + SUM_BYTES);
    unsigned char* stg  = smem_raw + SUM_BYTES + CNT_BYTES;

    const int tid  = threadIdx.x;
    const int warp = tid >> 5;
    const int lane = tid & 31;

    // Zero hist region (vectorized, conflict-free).
    {
        float4* h4 = (float4*)smem_raw;
        const int n4 = (SUM_BYTES + CNT_BYTES) / 16;
        for (int k = tid; k < n4; k += NT)
            h4[k] = make_float4(0.f, 0.f, 0.f, 0.f);
    }
    __syncthreads();

    float*    sum0 = sumh + tid;
    unsigned* cnt0 = cnth + tid;

    const float4* __restrict__ R = (const float4*)realp;
    const float4* __restrict__ F = (const float4*)fakep;
    const int4*   __restrict__ M = (const int4*)rmapp;

    const int T = GRID * NT;
    const int p0 = blockIdx.x * NT + tid;
    const uint32_t slot0 = smem_u32(stg) + tid * 16;

    // Prologue: fill ST stages (one commit group each).
    #pragma unroll
    for (int s = 0; s < ST; s++)
        stage_fill(slot0 + s * STG_STRIDE, R, F, M, p0 + s * T,
                   (p0 + s * T) < NV4);

    int pin = p0 + ST * T;     // next vec4 index to fetch
    int s   = 0;

    // Main loop: thread-private stages, no block barriers. wait_group ST-1
    // guarantees the oldest group (stage s) has landed; refill it, then
    // accumulate. Up to ST-1 later stages stay in flight during the consume.
    #pragma unroll 1
    for (int pc = p0; pc < NV4; pc += T) {
        asm volatile("cp.async.wait_group %0;" :: "n"(ST - 1) : "memory");

        const unsigned char* sb = stg + s * STG_STRIDE + tid * 16;
        float4 a = *(const float4*)(sb);
        float4 b = *(const float4*)(sb + STG_ARR);
        int4   m = *(const int4*)(sb + 2 * STG_ARR);

        stage_fill(slot0 + s * STG_STRIDE, R, F, M, pin, pin < NV4);
        pin += T;

        acc4(sum0, cnt0, a, b, m);
        if (++s == ST) s = 0;
    }
    asm volatile("cp.async.wait_all;" ::: "memory");

    __syncthreads();

    // Block reduction: warp w handles regions w, w+7, ... Lanes stride the
    // thread axis (conflict-free), then shfl-combine.
    for (int r = warp; r < NR; r += NW) {
        float    sv = 0.f;
        unsigned cv = 0;
        const int sh = (r & 1) << 4;
        #pragma unroll
        for (int k = 0; k < NT / 32; k++) {
            sv += sumh[r * NT + lane + k * 32];
            cv += (cnth[(r >> 1) * NT + lane + k * 32] >> sh) & 0xFFFFu;
        }
        #pragma unroll
        for (int o = 16; o; o >>= 1) {
            sv += __shfl_xor_sync(0xffffffffu, sv, o);
            cv += __shfl_xor_sync(0xffffffffu, cv, o);
        }
        if (lane == 0)
            g_part[blockIdx.x * NR + r] = make_float2(sv, (float)cv);
    }

    // ---- last-block finalize (threadfence-reduction pattern) ----
    __threadfence();
    __syncthreads();

    __shared__ unsigned is_last;
    if (tid == 0)
        is_last = (atomicAdd(&g_ticket, 1u) == GRID - 1) ? 1u : 0u;
    __syncthreads();
    if (!is_last)
        return;
    __threadfence();

    // Reuse hist smem for the 116-region final reduction.
    float* sh_s = (float*)smem_raw;
    float* sh_m = sh_s + NR;
    __shared__ float sh_max;

    if (tid < NR) {
        float sv = 0.f, cvf = 0.f;
        #pragma unroll 8
        for (int b = 0; b < GRID; b++) {
            float2 v = g_part[b * NR + tid];
            sv  += v.x;
            cvf += v.y;
        }
        sh_s[tid] = sv;
        sh_m[tid] = sv / (cvf + 1e-6f);
    }
    __syncthreads();

    if (tid < 32) {
        float mx = 0.f;   // running max starts at 0 (matches max(0, max_r m_r))
        for (int r = tid; r < NR; r += 32)
            mx = fmaxf(mx, sh_m[r]);
        #pragma unroll
        for (int o = 16; o; o >>= 1)
            mx = fmaxf(mx, __shfl_xor_sync(0xffffffffu, mx, o));
        if (tid == 0) sh_max = mx;
    }
    __syncthreads();

    if (tid < 32) {
        const float inv = 1e-3f / (sh_max + 1e-6f);
        float tot = 0.f;
        for (int r = tid; r < NR; r += 32)
            tot += sh_s[r] * (1.0f + inv * sh_m[r]);
        #pragma unroll
        for (int o = 16; o; o >>= 1)
            tot += __shfl_xor_sync(0xffffffffu, tot, o);
        if (tid == 0) {
            out[0] = tot / (float)NTOT;
            g_ticket = 0;       // reset for deterministic replay
        }
    }
}

extern "C" void kernel_launch(void* const* d_in, const int* in_sizes, int n_in,
                              void* d_out, int out_size)
{
    const float* realp = (const float*)d_in[0];
    const float* fakep = (const float*)d_in[1];
    const int*   rmapp = (const int*)d_in[2];

    cudaFuncSetAttribute(fused_kernel,
                         cudaFuncAttributeMaxDynamicSharedMemorySize,
                         SMEM_TOTAL);

    fused_kernel<<<GRID, NT, SMEM_TOTAL>>>(realp, fakep, rmapp, (float*)d_out);
}